// round 1
// baseline (speedup 1.0000x reference)
#include <cuda_runtime.h>
#include <math.h>

#define NPTS 16384
#define TILE 2048
#define BLOCK 256

// Packed points: (x, y, z, -0.5*(x^2+y^2+z^2)). [0:NPTS) = set A (d_in[0]),
// [NPTS:2*NPTS) = set B (d_in[1]).
__device__ float4 g_packed[2 * NPTS];
__device__ float g_acc;

__global__ void prep_kernel(const float* __restrict__ a,
                            const float* __restrict__ b) {
    int i = blockIdx.x * blockDim.x + threadIdx.x;
    if (i == 0) g_acc = 0.0f;   // re-zero every launch -> graph-replay safe
    if (i < NPTS) {
        float x = a[3 * i + 0], y = a[3 * i + 1], z = a[3 * i + 2];
        g_packed[i] = make_float4(x, y, z, -0.5f * (x * x + y * y + z * z));
        x = b[3 * i + 0]; y = b[3 * i + 1]; z = b[3 * i + 2];
        g_packed[NPTS + i] = make_float4(x, y, z, -0.5f * (x * x + y * y + z * z));
    }
}

// blockIdx.y = direction: 0 -> query = set B, ref = set A; 1 -> query = A, ref = B.
// Each thread owns one query point; refs streamed through shared tiles.
__global__ __launch_bounds__(BLOCK) void nn_kernel() {
    __shared__ float4 sh[TILE];
    __shared__ float red[BLOCK / 32];

    int dir = blockIdx.y;
    const float4* qbase = g_packed + (dir ? 0 : NPTS);
    const float4* rbase = g_packed + (dir ? NPTS : 0);

    int qi = blockIdx.x * BLOCK + threadIdx.x;
    float4 q = qbase[qi];

    // Track max over refs of e = q.r - 0.5*||r||^2 ; then d2min = q^2 - 2*max.
    float m0 = -1e30f, m1 = -1e30f, m2 = -1e30f, m3 = -1e30f;

    for (int t = 0; t < NPTS; t += TILE) {
        #pragma unroll
        for (int j = threadIdx.x; j < TILE; j += BLOCK)
            sh[j] = rbase[t + j];
        __syncthreads();

        #pragma unroll 4
        for (int j = 0; j < TILE; j += 4) {
            float4 r0 = sh[j + 0];
            float4 r1 = sh[j + 1];
            float4 r2 = sh[j + 2];
            float4 r3 = sh[j + 3];
            float e0 = fmaf(q.x, r0.x, fmaf(q.y, r0.y, fmaf(q.z, r0.z, r0.w)));
            float e1 = fmaf(q.x, r1.x, fmaf(q.y, r1.y, fmaf(q.z, r1.z, r1.w)));
            float e2 = fmaf(q.x, r2.x, fmaf(q.y, r2.y, fmaf(q.z, r2.z, r2.w)));
            float e3 = fmaf(q.x, r3.x, fmaf(q.y, r3.y, fmaf(q.z, r3.z, r3.w)));
            m0 = fmaxf(m0, e0);
            m1 = fmaxf(m1, e1);
            m2 = fmaxf(m2, e2);
            m3 = fmaxf(m3, e3);
        }
        __syncthreads();
    }

    float m = fmaxf(fmaxf(m0, m1), fmaxf(m2, m3));
    // q.w = -0.5*q^2  ->  d2 = q^2 - 2*m = -2*(q.w + m)
    float d2 = -2.0f * (q.w + m);
    float d = sqrtf(fmaxf(d2, 0.0f));

    // Block-wide sum reduction
    float v = d;
    #pragma unroll
    for (int o = 16; o > 0; o >>= 1)
        v += __shfl_down_sync(0xFFFFFFFFu, v, o);
    int lane = threadIdx.x & 31;
    int wid = threadIdx.x >> 5;
    if (lane == 0) red[wid] = v;
    __syncthreads();
    if (threadIdx.x < BLOCK / 32) {
        v = red[threadIdx.x];
        #pragma unroll
        for (int o = (BLOCK / 64); o > 0; o >>= 1)
            v += __shfl_down_sync(0xFFu, v, o);
        if (threadIdx.x == 0)
            atomicAdd(&g_acc, v);
    }
}

__global__ void final_kernel(float* out) {
    out[0] = g_acc * (1.0f / (2.0f * NPTS));
}

extern "C" void kernel_launch(void* const* d_in, const int* in_sizes, int n_in,
                              void* d_out, int out_size) {
    const float* a = (const float*)d_in[0];
    const float* b = (const float*)d_in[1];
    float* out = (float*)d_out;

    prep_kernel<<<(NPTS + 255) / 256, 256>>>(a, b);
    dim3 grid(NPTS / BLOCK, 2);
    nn_kernel<<<grid, BLOCK>>>();
    final_kernel<<<1, 1>>>(out);
}

// round 2
// speedup vs baseline: 1.5981x; 1.5981x over previous
#include <cuda_runtime.h>
#include <math.h>

#define NPTS 16384
#define TILE 2048              // refs per shared tile
#define BLOCK 224              // threads per block
#define QPT 2                  // queries per thread
#define QTILE (BLOCK * QPT)    // 448 queries per block
#define NQT 37                 // ceil(16384/448) query tiles per direction
#define NRS 4                  // ref splits
#define RCHUNK (NPTS / NRS)    // 4096 refs per split

// SoA packed points, per set: x,y,z and w = -0.5*(x^2+y^2+z^2)
__device__ float g_x[2][NPTS];
__device__ float g_y[2][NPTS];
__device__ float g_z[2][NPTS];
__device__ float g_w[2][NPTS];
// Order-encoded float max of e = q.r - 0.5*||r||^2, per query (dir*NPTS + qi)
__device__ int g_emax[2 * NPTS];
__device__ float g_acc;

// ---- packed f32x2 helpers ----
__device__ __forceinline__ unsigned long long fma2(unsigned long long a,
                                                   unsigned long long b,
                                                   unsigned long long c) {
    unsigned long long d;
    asm("fma.rn.f32x2 %0, %1, %2, %3;" : "=l"(d) : "l"(a), "l"(b), "l"(c));
    return d;
}
__device__ __forceinline__ unsigned long long pack2(float v) {
    unsigned long long d;
    asm("mov.b64 %0, {%1, %1};" : "=l"(d) : "f"(v));
    return d;
}
__device__ __forceinline__ void unpack2(unsigned long long p, float& lo, float& hi) {
    asm("mov.b64 {%0, %1}, %2;" : "=f"(lo), "=f"(hi) : "l"(p));
}

__device__ __forceinline__ int enc_float(float f) {
    int i = __float_as_int(f);
    return (i < 0) ? (i ^ 0x7FFFFFFF) : i;
}

__global__ void prep_kernel(const float* __restrict__ a,
                            const float* __restrict__ b) {
    int i = blockIdx.x * blockDim.x + threadIdx.x;
    if (i == 0) g_acc = 0.0f;
    if (i < NPTS) {
        float x = a[3 * i + 0], y = a[3 * i + 1], z = a[3 * i + 2];
        g_x[0][i] = x; g_y[0][i] = y; g_z[0][i] = z;
        g_w[0][i] = -0.5f * (x * x + y * y + z * z);
        x = b[3 * i + 0]; y = b[3 * i + 1]; z = b[3 * i + 2];
        g_x[1][i] = x; g_y[1][i] = y; g_z[1][i] = z;
        g_w[1][i] = -0.5f * (x * x + y * y + z * z);
        g_emax[i] = 0x80000000;
        g_emax[NPTS + i] = 0x80000000;
    }
}

// blockIdx.y = dir (query set = dir, ref set = 1-dir)
// blockIdx.x = rs * NQT + qt  (qt-major so concurrent blocks share ref chunk in L2)
__global__ __launch_bounds__(BLOCK, 2) void nn_kernel() {
    __shared__ __align__(16) float shx[TILE];
    __shared__ __align__(16) float shy[TILE];
    __shared__ __align__(16) float shz[TILE];
    __shared__ __align__(16) float shw[TILE];

    int dir = blockIdx.y;
    int qt = blockIdx.x % NQT;
    int rs = blockIdx.x / NQT;
    int qset = dir, rset = 1 - dir;

    const float* __restrict__ rx = g_x[rset] + rs * RCHUNK;
    const float* __restrict__ ry = g_y[rset] + rs * RCHUNK;
    const float* __restrict__ rz = g_z[rset] + rs * RCHUNK;
    const float* __restrict__ rw = g_w[rset] + rs * RCHUNK;

    int qi0 = qt * QTILE + threadIdx.x;
    int qi1 = qi0 + BLOCK;
    int c0 = min(qi0, NPTS - 1);   // clamped (dup work for last partial tile is harmless)
    int c1 = min(qi1, NPTS - 1);

    unsigned long long qx0 = pack2(g_x[qset][c0]);
    unsigned long long qy0 = pack2(g_y[qset][c0]);
    unsigned long long qz0 = pack2(g_z[qset][c0]);
    unsigned long long qx1 = pack2(g_x[qset][c1]);
    unsigned long long qy1 = pack2(g_y[qset][c1]);
    unsigned long long qz1 = pack2(g_z[qset][c1]);

    float m00 = -1e30f, m01 = -1e30f, m02 = -1e30f, m03 = -1e30f;
    float m10 = -1e30f, m11 = -1e30f, m12 = -1e30f, m13 = -1e30f;

    for (int t = 0; t < RCHUNK; t += TILE) {
        for (int j = threadIdx.x; j < TILE / 4; j += BLOCK) {
            ((float4*)shx)[j] = *(const float4*)&rx[t + 4 * j];
            ((float4*)shy)[j] = *(const float4*)&ry[t + 4 * j];
            ((float4*)shz)[j] = *(const float4*)&rz[t + 4 * j];
            ((float4*)shw)[j] = *(const float4*)&rw[t + 4 * j];
        }
        __syncthreads();

        #pragma unroll 2
        for (int j = 0; j < TILE; j += 4) {
            ulonglong2 xp = *(const ulonglong2*)&shx[j];
            ulonglong2 yp = *(const ulonglong2*)&shy[j];
            ulonglong2 zp = *(const ulonglong2*)&shz[j];
            ulonglong2 wp = *(const ulonglong2*)&shw[j];

            unsigned long long eA, eB;
            float lo, hi;

            // query 0
            eA = fma2(qx0, xp.x, fma2(qy0, yp.x, fma2(qz0, zp.x, wp.x)));
            eB = fma2(qx0, xp.y, fma2(qy0, yp.y, fma2(qz0, zp.y, wp.y)));
            unpack2(eA, lo, hi); m00 = fmaxf(m00, lo); m01 = fmaxf(m01, hi);
            unpack2(eB, lo, hi); m02 = fmaxf(m02, lo); m03 = fmaxf(m03, hi);

            // query 1
            eA = fma2(qx1, xp.x, fma2(qy1, yp.x, fma2(qz1, zp.x, wp.x)));
            eB = fma2(qx1, xp.y, fma2(qy1, yp.y, fma2(qz1, zp.y, wp.y)));
            unpack2(eA, lo, hi); m10 = fmaxf(m10, lo); m11 = fmaxf(m11, hi);
            unpack2(eB, lo, hi); m12 = fmaxf(m12, lo); m13 = fmaxf(m13, hi);
        }
        __syncthreads();
    }

    float m0 = fmaxf(fmaxf(m00, m01), fmaxf(m02, m03));
    float m1 = fmaxf(fmaxf(m10, m11), fmaxf(m12, m13));
    atomicMax(&g_emax[dir * NPTS + c0], enc_float(m0));
    atomicMax(&g_emax[dir * NPTS + c1], enc_float(m1));
}

__global__ void reduce_kernel() {
    __shared__ float red[8];
    int i = blockIdx.x * blockDim.x + threadIdx.x;   // 0 .. 2*NPTS-1
    int e = g_emax[i];
    if (e < 0) e ^= 0x7FFFFFFF;
    float m = __int_as_float(e);
    int dir = i >> 14;
    int qi = i & (NPTS - 1);
    float qw = g_w[dir][qi];
    float d2 = -2.0f * (qw + m);
    float v = sqrtf(fmaxf(d2, 0.0f));

    #pragma unroll
    for (int o = 16; o > 0; o >>= 1)
        v += __shfl_down_sync(0xFFFFFFFFu, v, o);
    int lane = threadIdx.x & 31;
    int wid = threadIdx.x >> 5;
    if (lane == 0) red[wid] = v;
    __syncthreads();
    if (threadIdx.x < 8) {
        v = red[threadIdx.x];
        #pragma unroll
        for (int o = 4; o > 0; o >>= 1)
            v += __shfl_down_sync(0xFFu, v, o);
        if (threadIdx.x == 0) atomicAdd(&g_acc, v);
    }
}

__global__ void out_kernel(float* out) {
    out[0] = g_acc * (1.0f / (2.0f * NPTS));
}

extern "C" void kernel_launch(void* const* d_in, const int* in_sizes, int n_in,
                              void* d_out, int out_size) {
    const float* a = (const float*)d_in[0];
    const float* b = (const float*)d_in[1];
    float* out = (float*)d_out;

    prep_kernel<<<(NPTS + 255) / 256, 256>>>(a, b);
    dim3 grid(NQT * NRS, 2);
    nn_kernel<<<grid, BLOCK>>>();
    reduce_kernel<<<(2 * NPTS) / 256, 256>>>();
    out_kernel<<<1, 1>>>(out);
}

// round 4
// speedup vs baseline: 1.6350x; 1.0231x over previous
#include <cuda_runtime.h>
#include <math.h>

#define NPTS 16384
#define TILE 2048              // refs per shared tile
#define BLOCK 224              // threads per block
#define QPT 2                  // queries per thread
#define QTILE (BLOCK * QPT)    // 448 queries per block
#define NQT 37                 // ceil(16384/448) query tiles per direction
#define NRS 4                  // ref splits
#define RCHUNK (NPTS / NRS)    // 4096 refs per split
#define FINBLK 256
#define NFIN ((2 * NPTS) / FINBLK)   // 128 fin blocks

// Partial maxes of e = q.r - 0.5*||r||^2 : [dir][refsplit][query]
__device__ float g_part[2][NRS][NPTS];
__device__ float g_bsum[NFIN];

typedef unsigned long long ull;

__device__ __forceinline__ ull fma2(ull a, ull b, ull c) {
    ull d;
    asm("fma.rn.f32x2 %0, %1, %2, %3;" : "=l"(d) : "l"(a), "l"(b), "l"(c));
    return d;
}
__device__ __forceinline__ ull pack2(float v) {
    ull d;
    asm("mov.b64 %0, {%1, %1};" : "=l"(d) : "f"(v));
    return d;
}
__device__ __forceinline__ void fmax2acc(ull e, float& a, float& b) {
    float lo, hi;
    asm("mov.b64 {%0, %1}, %2;" : "=f"(lo), "=f"(hi) : "l"(e));
    a = fmaxf(a, lo);
    b = fmaxf(b, hi);
}

// dir 0: queries = B, refs = A ; dir 1: queries = A, refs = B
__global__ __launch_bounds__(BLOCK, 2) void nn_kernel(const float* __restrict__ A,
                                                      const float* __restrict__ B) {
    __shared__ __align__(16) float shx[TILE];
    __shared__ __align__(16) float shy[TILE];
    __shared__ __align__(16) float shz[TILE];
    __shared__ __align__(16) float shw[TILE];

    int dir = blockIdx.y;
    int qt = blockIdx.x % NQT;
    int rs = blockIdx.x / NQT;
    const float* __restrict__ Q = dir ? A : B;
    const float* __restrict__ R = dir ? B : A;

    int qi0 = qt * QTILE + threadIdx.x;
    int c0 = min(qi0, NPTS - 1);          // clamp: duplicate work, benign same-value STG
    int c1 = min(qi0 + BLOCK, NPTS - 1);

    float q0x = Q[3 * c0], q0y = Q[3 * c0 + 1], q0z = Q[3 * c0 + 2];
    float q1x = Q[3 * c1], q1y = Q[3 * c1 + 1], q1z = Q[3 * c1 + 2];
    ull qx0 = pack2(q0x), qy0 = pack2(q0y), qz0 = pack2(q0z);
    ull qx1 = pack2(q1x), qy1 = pack2(q1y), qz1 = pack2(q1z);

    float m0 = -1e30f, m1 = -1e30f, m2 = -1e30f, m3 = -1e30f;
    float m4 = -1e30f, m5 = -1e30f, m6 = -1e30f, m7 = -1e30f;
    float n0 = -1e30f, n1 = -1e30f, n2 = -1e30f, n3 = -1e30f;
    float n4 = -1e30f, n5 = -1e30f, n6 = -1e30f, n7 = -1e30f;

    for (int t = rs * RCHUNK; t < rs * RCHUNK + RCHUNK; t += TILE) {
        // Tile fill: raw AoS coords -> SoA shared + w = -0.5*||r||^2
        for (int p = threadIdx.x; p < TILE; p += BLOCK) {
            int g = t + p;
            float x = R[3 * g], y = R[3 * g + 1], z = R[3 * g + 2];
            shx[p] = x; shy[p] = y; shz[p] = z;
            shw[p] = -0.5f * (x * x + y * y + z * z);
        }
        __syncthreads();

        const ulonglong2* px = (const ulonglong2*)shx;
        const ulonglong2* py = (const ulonglong2*)shy;
        const ulonglong2* pz = (const ulonglong2*)shz;
        const ulonglong2* pw = (const ulonglong2*)shw;

        #pragma unroll 2
        for (int j4 = 0; j4 < TILE / 4; j4 += 2) {
            ulonglong2 X0 = px[j4], X1 = px[j4 + 1];
            ulonglong2 Y0 = py[j4], Y1 = py[j4 + 1];
            ulonglong2 Z0 = pz[j4], Z1 = pz[j4 + 1];
            ulonglong2 W0 = pw[j4], W1 = pw[j4 + 1];

            ull e;
            // query 0
            e = fma2(qx0, X0.x, fma2(qy0, Y0.x, fma2(qz0, Z0.x, W0.x))); fmax2acc(e, m0, m1);
            e = fma2(qx0, X0.y, fma2(qy0, Y0.y, fma2(qz0, Z0.y, W0.y))); fmax2acc(e, m2, m3);
            e = fma2(qx0, X1.x, fma2(qy0, Y1.x, fma2(qz0, Z1.x, W1.x))); fmax2acc(e, m4, m5);
            e = fma2(qx0, X1.y, fma2(qy0, Y1.y, fma2(qz0, Z1.y, W1.y))); fmax2acc(e, m6, m7);
            // query 1
            e = fma2(qx1, X0.x, fma2(qy1, Y0.x, fma2(qz1, Z0.x, W0.x))); fmax2acc(e, n0, n1);
            e = fma2(qx1, X0.y, fma2(qy1, Y0.y, fma2(qz1, Z0.y, W0.y))); fmax2acc(e, n2, n3);
            e = fma2(qx1, X1.x, fma2(qy1, Y1.x, fma2(qz1, Z1.x, W1.x))); fmax2acc(e, n4, n5);
            e = fma2(qx1, X1.y, fma2(qy1, Y1.y, fma2(qz1, Z1.y, W1.y))); fmax2acc(e, n6, n7);
        }
        __syncthreads();
    }

    float ma = fmaxf(fmaxf(fmaxf(m0, m1), fmaxf(m2, m3)),
                     fmaxf(fmaxf(m4, m5), fmaxf(m6, m7)));
    float mb = fmaxf(fmaxf(fmaxf(n0, n1), fmaxf(n2, n3)),
                     fmaxf(fmaxf(n4, n5), fmaxf(n6, n7)));
    g_part[dir][rs][c0] = ma;
    g_part[dir][rs][c1] = mb;
}

// One thread per (dir, query): combine NRS partials, d = sqrt(-2*(qw + m)), block-sum.
__global__ void fin_kernel(const float* __restrict__ A, const float* __restrict__ B) {
    __shared__ float red[FINBLK / 32];
    int i = blockIdx.x * FINBLK + threadIdx.x;   // 0 .. 2*NPTS-1
    int dir = i >> 14;
    int qi = i & (NPTS - 1);
    const float* __restrict__ Q = dir ? A : B;

    float m = g_part[dir][0][qi];
    #pragma unroll
    for (int rs = 1; rs < NRS; rs++) m = fmaxf(m, g_part[dir][rs][qi]);

    float x = Q[3 * qi], y = Q[3 * qi + 1], z = Q[3 * qi + 2];
    float qw = -0.5f * (x * x + y * y + z * z);
    float d2 = -2.0f * (qw + m);
    float v = sqrtf(fmaxf(d2, 0.0f));

    #pragma unroll
    for (int o = 16; o > 0; o >>= 1) v += __shfl_down_sync(0xFFFFFFFFu, v, o);
    int lane = threadIdx.x & 31, wid = threadIdx.x >> 5;
    if (lane == 0) red[wid] = v;
    __syncthreads();
    if (threadIdx.x < FINBLK / 32) {
        v = red[threadIdx.x];
        #pragma unroll
        for (int o = FINBLK / 64; o > 0; o >>= 1) v += __shfl_down_sync(0xFFu, v, o);
        if (threadIdx.x == 0) g_bsum[blockIdx.x] = v;
    }
}

__global__ void out_kernel(float* __restrict__ out) {
    __shared__ float red[NFIN / 32];
    float v = g_bsum[threadIdx.x];
    #pragma unroll
    for (int o = 16; o > 0; o >>= 1) v += __shfl_down_sync(0xFFFFFFFFu, v, o);
    int lane = threadIdx.x & 31, wid = threadIdx.x >> 5;
    if (lane == 0) red[wid] = v;
    __syncthreads();
    if (threadIdx.x == 0) {
        float s = 0.0f;
        #pragma unroll
        for (int w = 0; w < NFIN / 32; w++) s += red[w];
        out[0] = s * (1.0f / (2.0f * NPTS));
    }
}

extern "C" void kernel_launch(void* const* d_in, const int* in_sizes, int n_in,
                              void* d_out, int out_size) {
    const float* a = (const float*)d_in[0];
    const float* b = (const float*)d_in[1];
    float* out = (float*)d_out;

    dim3 grid(NQT * NRS, 2);
    nn_kernel<<<grid, BLOCK>>>(a, b);
    fin_kernel<<<NFIN, FINBLK>>>(a, b);
    out_kernel<<<1, NFIN>>>(out);
}

// round 5
// speedup vs baseline: 1.9017x; 1.1632x over previous
#include <cuda_runtime.h>
#include <math.h>

#define NPTS 16384
#define TILE 2048              // refs per block = one shared tile
#define BLOCK 224              // threads per block
#define QPT 2                  // queries per thread
#define QTILE (BLOCK * QPT)    // 448 queries per block
#define NQT 37                 // ceil(16384/448) query tiles per direction
#define NRS 8                  // ref splits -> grid = 37*8*2 = 592 = 4 blocks/SM
#define FINBLK 256
#define NFIN ((2 * NPTS) / FINBLK)   // 128 fin blocks

// Partial maxes of e = q.r - 0.5*||r||^2 : [dir][refsplit][query]
__device__ float g_part[2][NRS][NPTS];
__device__ float g_bsum[NFIN];

typedef unsigned long long ull;

__device__ __forceinline__ ull fma2(ull a, ull b, ull c) {
    ull d;
    asm("fma.rn.f32x2 %0, %1, %2, %3;" : "=l"(d) : "l"(a), "l"(b), "l"(c));
    return d;
}
__device__ __forceinline__ ull pack2(float v) {
    ull d;
    asm("mov.b64 %0, {%1, %1};" : "=l"(d) : "f"(v));
    return d;
}
__device__ __forceinline__ void fmax2acc(ull e, float& a, float& b) {
    float lo, hi;
    asm("mov.b64 {%0, %1}, %2;" : "=f"(lo), "=f"(hi) : "l"(e));
    a = fmaxf(a, lo);
    b = fmaxf(b, hi);
}

// dir 0: queries = B, refs = A ; dir 1: queries = A, refs = B
__global__ __launch_bounds__(BLOCK, 4) void nn_kernel(const float* __restrict__ A,
                                                      const float* __restrict__ B) {
    __shared__ __align__(16) float shx[TILE];
    __shared__ __align__(16) float shy[TILE];
    __shared__ __align__(16) float shz[TILE];
    __shared__ __align__(16) float shw[TILE];

    int dir = blockIdx.y;
    int qt = blockIdx.x % NQT;
    int rs = blockIdx.x / NQT;
    const float* __restrict__ Q = dir ? A : B;
    const float* __restrict__ R = dir ? B : A;

    int qi0 = qt * QTILE + threadIdx.x;
    int c0 = min(qi0, NPTS - 1);          // clamp: duplicate work, benign same-value STG
    int c1 = min(qi0 + BLOCK, NPTS - 1);

    float q0x = Q[3 * c0], q0y = Q[3 * c0 + 1], q0z = Q[3 * c0 + 2];
    float q1x = Q[3 * c1], q1y = Q[3 * c1 + 1], q1z = Q[3 * c1 + 2];
    ull qx0 = pack2(q0x), qy0 = pack2(q0y), qz0 = pack2(q0z);
    ull qx1 = pack2(q1x), qy1 = pack2(q1y), qz1 = pack2(q1z);

    // Tile fill: raw AoS coords -> SoA shared + w = -0.5*||r||^2
    {
        int t0 = rs * TILE;
        for (int p = threadIdx.x; p < TILE; p += BLOCK) {
            int g = t0 + p;
            float x = R[3 * g], y = R[3 * g + 1], z = R[3 * g + 2];
            shx[p] = x; shy[p] = y; shz[p] = z;
            shw[p] = -0.5f * (x * x + y * y + z * z);
        }
    }
    __syncthreads();

    float m0 = -1e30f, m1 = -1e30f, m2 = -1e30f, m3 = -1e30f;
    float n0 = -1e30f, n1 = -1e30f, n2 = -1e30f, n3 = -1e30f;

    const ulonglong2* px = (const ulonglong2*)shx;
    const ulonglong2* py = (const ulonglong2*)shy;
    const ulonglong2* pz = (const ulonglong2*)shz;
    const ulonglong2* pw = (const ulonglong2*)shw;

    #pragma unroll 4
    for (int j4 = 0; j4 < TILE / 4; j4++) {
        ulonglong2 X = px[j4];
        ulonglong2 Y = py[j4];
        ulonglong2 Z = pz[j4];
        ulonglong2 W = pw[j4];

        ull e;
        // query 0 (4 refs)
        e = fma2(qx0, X.x, fma2(qy0, Y.x, fma2(qz0, Z.x, W.x))); fmax2acc(e, m0, m1);
        e = fma2(qx0, X.y, fma2(qy0, Y.y, fma2(qz0, Z.y, W.y))); fmax2acc(e, m2, m3);
        // query 1 (same 4 refs)
        e = fma2(qx1, X.x, fma2(qy1, Y.x, fma2(qz1, Z.x, W.x))); fmax2acc(e, n0, n1);
        e = fma2(qx1, X.y, fma2(qy1, Y.y, fma2(qz1, Z.y, W.y))); fmax2acc(e, n2, n3);
    }

    float ma = fmaxf(fmaxf(m0, m1), fmaxf(m2, m3));
    float mb = fmaxf(fmaxf(n0, n1), fmaxf(n2, n3));
    g_part[dir][rs][c0] = ma;
    g_part[dir][rs][c1] = mb;
}

// One thread per (dir, query): combine NRS partials, d = sqrt(-2*(qw + m)), block-sum.
__global__ void fin_kernel(const float* __restrict__ A, const float* __restrict__ B) {
    __shared__ float red[FINBLK / 32];
    int i = blockIdx.x * FINBLK + threadIdx.x;   // 0 .. 2*NPTS-1
    int dir = i >> 14;
    int qi = i & (NPTS - 1);
    const float* __restrict__ Q = dir ? A : B;

    float m = g_part[dir][0][qi];
    #pragma unroll
    for (int rs = 1; rs < NRS; rs++) m = fmaxf(m, g_part[dir][rs][qi]);

    float x = Q[3 * qi], y = Q[3 * qi + 1], z = Q[3 * qi + 2];
    float qw = -0.5f * (x * x + y * y + z * z);
    float d2 = -2.0f * (qw + m);
    float v = sqrtf(fmaxf(d2, 0.0f));

    #pragma unroll
    for (int o = 16; o > 0; o >>= 1) v += __shfl_down_sync(0xFFFFFFFFu, v, o);
    int lane = threadIdx.x & 31, wid = threadIdx.x >> 5;
    if (lane == 0) red[wid] = v;
    __syncthreads();
    if (threadIdx.x < FINBLK / 32) {
        v = red[threadIdx.x];
        #pragma unroll
        for (int o = FINBLK / 64; o > 0; o >>= 1) v += __shfl_down_sync(0xFFu, v, o);
        if (threadIdx.x == 0) g_bsum[blockIdx.x] = v;
    }
}

__global__ void out_kernel(float* __restrict__ out) {
    __shared__ float red[NFIN / 32];
    float v = g_bsum[threadIdx.x];
    #pragma unroll
    for (int o = 16; o > 0; o >>= 1) v += __shfl_down_sync(0xFFFFFFFFu, v, o);
    int lane = threadIdx.x & 31, wid = threadIdx.x >> 5;
    if (lane == 0) red[wid] = v;
    __syncthreads();
    if (threadIdx.x == 0) {
        float s = 0.0f;
        #pragma unroll
        for (int w = 0; w < NFIN / 32; w++) s += red[w];
        out[0] = s * (1.0f / (2.0f * NPTS));
    }
}

extern "C" void kernel_launch(void* const* d_in, const int* in_sizes, int n_in,
                              void* d_out, int out_size) {
    const float* a = (const float*)d_in[0];
    const float* b = (const float*)d_in[1];
    float* out = (float*)d_out;

    dim3 grid(NQT * NRS, 2);
    nn_kernel<<<grid, BLOCK>>>(a, b);
    fin_kernel<<<NFIN, FINBLK>>>(a, b);
    out_kernel<<<1, NFIN>>>(out);
}

// round 6
// speedup vs baseline: 3.4147x; 1.7956x over previous
#include <cuda_runtime.h>
#include <math.h>

#define NPTS 16384
#define NCELL 24
#define NCELL2 (NCELL * NCELL)
#define NCELL3 (NCELL * NCELL * NCELL)     // 13824
#define GRIDF 128.0f
#define INV_CELL (NCELL / 128.0f)          // 0.1875f
#define CELLSZ (128.0f / NCELL)            // 5.3333f
#define SCAN_T 1024
#define CHUNK ((NCELL3 + SCAN_T - 1) / SCAN_T)   // 14
#define QBLK 256

__device__ int g_cnt[2][NCELL3];
__device__ int g_start[2][NCELL3 + 1];
__device__ int g_cursor[2][NCELL3];
__device__ float4 g_pts[2][NPTS];          // sorted by cell; w = -0.5*||p||^2
__device__ float g_acc;

__device__ __forceinline__ int cell_of(float x, float y, float z) {
    int cx = min((int)(x * INV_CELL), NCELL - 1);
    int cy = min((int)(y * INV_CELL), NCELL - 1);
    int cz = min((int)(z * INV_CELL), NCELL - 1);
    return (cx * NCELL + cy) * NCELL + cz;
}

__global__ void zero_kernel() {
    int i = blockIdx.x * blockDim.x + threadIdx.x;
    if (i == 0) g_acc = 0.0f;
    if (i < 2 * NCELL3) ((int*)g_cnt)[i] = 0;
}

__global__ void count_kernel(const float* __restrict__ A,
                             const float* __restrict__ B) {
    int i = blockIdx.x * blockDim.x + threadIdx.x;   // 0 .. 2*NPTS-1
    int set = i >> 14;
    int idx = i & (NPTS - 1);
    const float* __restrict__ P = set ? B : A;
    float x = P[3 * idx], y = P[3 * idx + 1], z = P[3 * idx + 2];
    atomicAdd(&g_cnt[set][cell_of(x, y, z)], 1);
}

// One block per set: exclusive scan of 13824 counts.
__global__ void scan_kernel() {
    __shared__ int sh[SCAN_T];
    int set = blockIdx.x;
    int t = threadIdx.x;
    int base = t * CHUNK;

    int sum = 0;
    #pragma unroll
    for (int u = 0; u < CHUNK; u++) {
        int c = base + u;
        if (c < NCELL3) sum += g_cnt[set][c];
    }
    sh[t] = sum;
    __syncthreads();
    // Hillis-Steele inclusive scan over thread sums
    for (int off = 1; off < SCAN_T; off <<= 1) {
        int v = sh[t];
        int w = (t >= off) ? sh[t - off] : 0;
        __syncthreads();
        sh[t] = v + w;
        __syncthreads();
    }
    int excl = (t == 0) ? 0 : sh[t - 1];
    #pragma unroll
    for (int u = 0; u < CHUNK; u++) {
        int c = base + u;
        if (c < NCELL3) {
            g_start[set][c] = excl;
            g_cursor[set][c] = excl;
            excl += g_cnt[set][c];
        }
    }
    if (t == SCAN_T - 1) g_start[set][NCELL3] = excl;   // = NPTS
}

__global__ void scatter_kernel(const float* __restrict__ A,
                               const float* __restrict__ B) {
    int i = blockIdx.x * blockDim.x + threadIdx.x;
    int set = i >> 14;
    int idx = i & (NPTS - 1);
    const float* __restrict__ P = set ? B : A;
    float x = P[3 * idx], y = P[3 * idx + 1], z = P[3 * idx + 2];
    int c = cell_of(x, y, z);
    int pos = atomicAdd(&g_cursor[set][c], 1);
    g_pts[set][pos] = make_float4(x, y, z, -0.5f * (x * x + y * y + z * z));
}

// One thread per sorted query (both directions). Warp = spatially-coherent queries.
__global__ __launch_bounds__(QBLK) void query_kernel() {
    __shared__ float red[QBLK / 32];
    int i = blockIdx.x * QBLK + threadIdx.x;   // 0 .. 2*NPTS-1
    int qs = i >> 14;                          // query set
    int rs = qs ^ 1;                           // ref set
    int idx = i & (NPTS - 1);

    float4 q = g_pts[qs][idx];
    int cx = min((int)(q.x * INV_CELL), NCELL - 1);
    int cy = min((int)(q.y * INV_CELL), NCELL - 1);
    int cz = min((int)(q.z * INV_CELL), NCELL - 1);

    const int* __restrict__ start = g_start[rs];
    const float4* __restrict__ pts = g_pts[rs];

    float best = -1e30f;   // max over refs of e = q.r - 0.5*||r||^2
    for (int r = 1; r <= NCELL; r++) {
        int x0 = max(cx - r, 0), x1 = min(cx + r, NCELL - 1);
        int y0 = max(cy - r, 0), y1 = min(cy + r, NCELL - 1);
        int z0 = max(cz - r, 0), z1 = min(cz + r, NCELL - 1);
        for (int ix = x0; ix <= x1; ix++) {
            for (int iy = y0; iy <= y1; iy++) {
                int base = (ix * NCELL + iy) * NCELL;
                int p0 = start[base + z0];
                int p1 = start[base + z1 + 1];   // z-contiguous span of cells
                for (int p = p0; p < p1; p++) {
                    float4 t = pts[p];
                    float e = fmaf(q.x, t.x, fmaf(q.y, t.y, fmaf(q.z, t.z, t.w)));
                    best = fmaxf(best, e);
                }
            }
        }
        float d2 = -2.0f * (q.w + best);
        float rb = r * CELLSZ;
        if (d2 <= rb * rb) break;   // all unscanned points are strictly farther
    }

    float d2 = -2.0f * (q.w + best);
    float v = sqrtf(fmaxf(d2, 0.0f));

    #pragma unroll
    for (int o = 16; o > 0; o >>= 1) v += __shfl_down_sync(0xFFFFFFFFu, v, o);
    int lane = threadIdx.x & 31, wid = threadIdx.x >> 5;
    if (lane == 0) red[wid] = v;
    __syncthreads();
    if (threadIdx.x < QBLK / 32) {
        v = red[threadIdx.x];
        #pragma unroll
        for (int o = QBLK / 64; o > 0; o >>= 1) v += __shfl_down_sync(0xFFu, v, o);
        if (threadIdx.x == 0) atomicAdd(&g_acc, v);
    }
}

__global__ void out_kernel(float* __restrict__ out) {
    out[0] = g_acc * (1.0f / (2.0f * NPTS));
}

extern "C" void kernel_launch(void* const* d_in, const int* in_sizes, int n_in,
                              void* d_out, int out_size) {
    const float* a = (const float*)d_in[0];
    const float* b = (const float*)d_in[1];
    float* out = (float*)d_out;

    zero_kernel<<<(2 * NCELL3 + 255) / 256, 256>>>();
    count_kernel<<<(2 * NPTS) / 256, 256>>>(a, b);
    scan_kernel<<<2, SCAN_T>>>();
    scatter_kernel<<<(2 * NPTS) / 256, 256>>>(a, b);
    query_kernel<<<(2 * NPTS) / QBLK, QBLK>>>();
    out_kernel<<<1, 1>>>(out);
}